// round 2
// baseline (speedup 1.0000x reference)
#include <cuda_runtime.h>
#include <math.h>

#define B      8
#define DIM    1024
#define DIM2   2048
#define HID    512
#define NB     16
#define SEQ    2048
#define TLEN   4096
#define NSTEPS (TLEN - SEQ)
#define NBLK   128
#define NTHR   512
#define VSTRIDE 2049                       // padded row stride: 8 batches -> 8 distinct banks
#define REDSZ   2048
#define SMEM_FLOATS (B * VSTRIDE + REDSZ + 128)

// ---------------- persistent state (device globals; no allocs) ----------------
__device__ float g_h1[B * DIM];
__device__ float g_nxt[B * DIM];
__device__ float g_hist[2][B * DIM];       // ping-pong corrected "cur" history
__device__ float g_coef[2][B * NB];        // double-buffered coef accumulators
__device__ unsigned long long g_gen = 0;   // barrier generation (monotonic across replays)
__device__ unsigned int       g_cnt = 0;   // barrier arrival counter (self-resetting)

// ---------------- grid barrier ----------------
__device__ __forceinline__ unsigned long long ld_acq(unsigned long long* p) {
    unsigned long long v;
    asm volatile("ld.acquire.gpu.global.u64 %0, [%1];" : "=l"(v) : "l"(p) : "memory");
    return v;
}
__device__ __forceinline__ void st_rel(unsigned long long* p, unsigned long long v) {
    asm volatile("st.release.gpu.global.u64 [%0], %1;" :: "l"(p), "l"(v) : "memory");
}
__device__ __forceinline__ void grid_barrier() {
    __syncthreads();
    if (threadIdx.x == 0) {
        unsigned long long my = ld_acq(&g_gen);
        __threadfence();
        if (atomicAdd(&g_cnt, 1u) == NBLK - 1) {
            g_cnt = 0;                       // ordered before gen flip by st.release
            st_rel(&g_gen, my + 1);
        } else {
            while (ld_acq(&g_gen) == my) { __nanosleep(32); }
        }
    }
    __syncthreads();
}

// ---------------- prefix copy: out[:, 0:2048, :] = x ----------------
__global__ void copy_kernel(const float4* __restrict__ x4, float4* __restrict__ out4) {
    size_t q = (size_t)blockIdx.x * blockDim.x + threadIdx.x;   // 0 .. 8*2048*256-1
    int b = (int)(q >> 19);                 // 2048*256 float4 per batch
    size_t r = q & 524287;
    out4[((size_t)b << 20) + r] = x4[q];    // 4096*256 float4 per out batch
}

// ---------------- persistent extrapolation kernel ----------------
__global__ void __launch_bounds__(NTHR, 1)
extrap_kernel(const float* __restrict__ x,
              const float* __restrict__ basis,
              const float* __restrict__ W1,
              const float* __restrict__ b1,
              const float* __restrict__ W2,
              const float* __restrict__ b2,
              const float* __restrict__ D1,
              const float* __restrict__ bD1,
              const float* __restrict__ D2,
              const float* __restrict__ bD2,
              float* __restrict__ out)
{
    extern __shared__ float smem[];
    float* s_vin  = smem;                   // [B][VSTRIDE]: cur @ [0..1023], prev/h1/nxt @ [1024..2047]
    float* s_red  = smem + B * VSTRIDE;     // REDSZ floats reduction scratch
    float* s_coef = s_red + REDSZ;          // 128 floats

    const int bid = blockIdx.x;
    const int t   = threadIdx.x;

    for (int s = 0; s < NSTEPS; ++s) {
        // ================= prologue: materialize cur (corrected) & prev =================
        if (s == 0) {
            for (int idx = t; idx < B * DIM; idx += NTHR) {
                int b = idx >> 10, k = idx & (DIM - 1);
                s_vin[b * VSTRIDE + k]       = x[((size_t)b * SEQ + (SEQ - 1)) * DIM + k];
                s_vin[b * VSTRIDE + DIM + k] = x[((size_t)b * SEQ + (SEQ - 2)) * DIM + k];
            }
            if (t < 64) {                    // hist[0] = cur_0 (prev for step 1)
                int b = t >> 3, kk = bid * 8 + (t & 7);
                g_hist[0][b * DIM + kk] = x[((size_t)b * SEQ + (SEQ - 1)) * DIM + kk];
            }
            if (bid == 0 && t < 2 * B * NB) ((float*)g_coef)[t] = 0.f;
        } else {
            const int par = (s - 1) & 1;
            if (t < B * NB) s_coef[t] = g_coef[par][t] + b2[t & (NB - 1)];
            __syncthreads();
            #pragma unroll
            for (int pass = 0; pass < DIM / NTHR; ++pass) {
                int k = pass * NTHR + t;
                float bas[NB];
                #pragma unroll
                for (int c = 0; c < NB; ++c) bas[c] = basis[c * DIM + k];
                #pragma unroll
                for (int b = 0; b < B; ++b) {
                    float acc = g_nxt[b * DIM + k];
                    #pragma unroll
                    for (int c = 0; c < NB; ++c) acc += 0.1f * s_coef[b * NB + c] * bas[c];
                    s_vin[b * VSTRIDE + k]       = acc;                        // cur_s
                    s_vin[b * VSTRIDE + DIM + k] = g_hist[par][b * DIM + k];   // prev_s
                }
            }
            __syncthreads();
            if (t < 64) {                    // owner writes corrected row to hist + output
                int b = t >> 3, kk = bid * 8 + (t & 7);
                float v = s_vin[b * VSTRIDE + kk];
                g_hist[s & 1][b * DIM + kk] = v;
                out[((size_t)b * TLEN + (SEQ + s - 1)) * DIM + kk] = v;
            }
        }
        __syncthreads();

        // ================= phase 1: h1 = tanh([cur,prev] @ D1 + bD1), 8 cols/block =================
        {
            const int jbase = bid * 8;
            const int cg = t & 1;            // column group of 4
            const int b  = (t >> 1) & 7;
            const int ks = t >> 4;           // 0..31, 64 k each
            const float* vrow = s_vin + b * VSTRIDE;
            const int j0 = jbase + cg * 4;
            float a0 = 0.f, a1 = 0.f, a2 = 0.f, a3 = 0.f;
            const int k0 = ks * 64;
            #pragma unroll 8
            for (int k = k0; k < k0 + 64; ++k) {
                float xv = vrow[k];
                float4 w = __ldg(reinterpret_cast<const float4*>(D1 + ((size_t)k << 10) + j0));
                a0 += xv * w.x; a1 += xv * w.y; a2 += xv * w.z; a3 += xv * w.w;
            }
            reinterpret_cast<float4*>(s_red)[(cg * 8 + b) * 32 + ks] = make_float4(a0, a1, a2, a3);
        }
        __syncthreads();
        if (t < 64) {
            int pg = t >> 2, ci = t & 3;
            int cg = pg >> 3, b = pg & 7;
            float sum = 0.f;
            #pragma unroll
            for (int kk = 0; kk < 32; ++kk) sum += s_red[(pg * 32 + kk) * 4 + ci];
            int j = bid * 8 + cg * 4 + ci;
            g_h1[b * DIM + j] = tanhf(sum + bD1[j]);
        }
        grid_barrier();
        if (bid == 0 && t < B * NB) g_coef[(s + 1) & 1][t] = 0.f;   // safe: prologue reads done

        // stage h1 into smem (second half)
        for (int idx = t; idx < B * DIM; idx += NTHR) {
            int b = idx >> 10, j = idx & (DIM - 1);
            s_vin[b * VSTRIDE + DIM + j] = g_h1[idx];
        }
        __syncthreads();

        // ================= phase 2: nxt = cur + h1 @ D2 + bD2, 8 cols/block =================
        {
            const int ibase = bid * 8;
            const int cg = t & 1, b = (t >> 1) & 7, ks = t >> 4;   // 32 slices, 32 k each
            const float* hrow = s_vin + b * VSTRIDE + DIM;
            const int i0 = ibase + cg * 4;
            float a0 = 0.f, a1 = 0.f, a2 = 0.f, a3 = 0.f;
            const int k0 = ks * 32;
            #pragma unroll 8
            for (int k = k0; k < k0 + 32; ++k) {
                float hv = hrow[k];
                float4 w = __ldg(reinterpret_cast<const float4*>(D2 + ((size_t)k << 10) + i0));
                a0 += hv * w.x; a1 += hv * w.y; a2 += hv * w.z; a3 += hv * w.w;
            }
            reinterpret_cast<float4*>(s_red)[(cg * 8 + b) * 32 + ks] = make_float4(a0, a1, a2, a3);
        }
        __syncthreads();
        if (t < 64) {
            int pg = t >> 2, ci = t & 3;
            int cg = pg >> 3, b = pg & 7;
            float sum = 0.f;
            #pragma unroll
            for (int kk = 0; kk < 32; ++kk) sum += s_red[(pg * 32 + kk) * 4 + ci];
            int i = bid * 8 + cg * 4 + ci;
            g_nxt[b * DIM + i] = s_vin[b * VSTRIDE + i] + sum + bD2[i];
        }
        grid_barrier();

        // stage nxt into smem (second half)
        for (int idx = t; idx < B * DIM; idx += NTHR) {
            int b = idx >> 10, i = idx & (DIM - 1);
            s_vin[b * VSTRIDE + DIM + i] = g_nxt[idx];
        }
        __syncthreads();

        // ================= phase 3/4: g = gelu(nxt@W1+b1); coef += g@W2 (4 cols/block) =================
        {
            const int mbase = bid * 4;
            const int b = t & 7, ks = t >> 3;   // 64 slices, 16 k each
            const float* nrow = s_vin + b * VSTRIDE + DIM;
            float a0 = 0.f, a1 = 0.f, a2 = 0.f, a3 = 0.f;
            const int k0 = ks * 16;
            #pragma unroll
            for (int k = k0; k < k0 + 16; ++k) {
                float nv = nrow[k];
                float4 w = __ldg(reinterpret_cast<const float4*>(W1 + (size_t)k * HID + mbase));
                a0 += nv * w.x; a1 += nv * w.y; a2 += nv * w.z; a3 += nv * w.w;
            }
            reinterpret_cast<float4*>(s_red)[b * 64 + ks] = make_float4(a0, a1, a2, a3);
        }
        __syncthreads();
        if (t < 32) {
            int b = t >> 2, mi = t & 3;
            float sum = 0.f;
            #pragma unroll
            for (int kk = 0; kk < 64; ++kk) sum += s_red[(b * 64 + kk) * 4 + mi];
            int m = bid * 4 + mi;
            float z = sum + b1[m];
            s_coef[t] = 0.5f * z * (1.0f + erff(z * 0.70710678118654752f));  // exact gelu
        }
        __syncthreads();
        if (t < B * NB) {
            int b = t >> 4, c = t & (NB - 1);
            float acc = 0.f;
            #pragma unroll
            for (int mi = 0; mi < 4; ++mi)
                acc += s_coef[b * 4 + mi] * __ldg(W2 + (size_t)(bid * 4 + mi) * NB + c);
            atomicAdd(&g_coef[s & 1][t], acc);
        }
        grid_barrier();
    }

    // ================= epilogue: final corrected row (t = TLEN-1) =================
    {
        const int par = (NSTEPS - 1) & 1;
        if (t < B * NB) s_coef[t] = g_coef[par][t] + b2[t & (NB - 1)];
        __syncthreads();
        if (t < 64) {
            int b = t >> 3, kk = bid * 8 + (t & 7);
            float acc = g_nxt[b * DIM + kk];
            #pragma unroll
            for (int c = 0; c < NB; ++c) acc += 0.1f * s_coef[b * NB + c] * basis[c * DIM + kk];
            out[((size_t)b * TLEN + (TLEN - 1)) * DIM + kk] = acc;
        }
    }
}

// ---------------- launch ----------------
extern "C" void kernel_launch(void* const* d_in, const int* in_sizes, int n_in,
                              void* d_out, int out_size) {
    const float* x     = (const float*)d_in[0];
    const float* basis = (const float*)d_in[1];
    const float* W1    = (const float*)d_in[2];
    const float* b1    = (const float*)d_in[3];
    const float* W2    = (const float*)d_in[4];
    const float* b2v   = (const float*)d_in[5];
    const float* D1    = (const float*)d_in[6];
    const float* bD1   = (const float*)d_in[7];
    const float* D2    = (const float*)d_in[8];
    const float* bD2   = (const float*)d_in[9];
    float* out = (float*)d_out;

    // prefix: out[:, 0:2048, :] = x   (8*2048*256 float4 = 4096 * 1024 threads)
    copy_kernel<<<4096, 1024>>>((const float4*)x, (float4*)out);

    size_t smem_bytes = (size_t)SMEM_FLOATS * sizeof(float);   // ~74.3 KB
    cudaFuncSetAttribute(extrap_kernel, cudaFuncAttributeMaxDynamicSharedMemorySize,
                         (int)smem_bytes);
    extrap_kernel<<<NBLK, NTHR, smem_bytes>>>(x, basis, W1, b1, W2, b2v,
                                              D1, bD1, D2, bD2, out);
}

// round 3
// speedup vs baseline: 1.0003x; 1.0003x over previous
#include <cuda_runtime.h>
#include <math.h>

#define B      8
#define DIM    1024
#define DIM2   2048
#define HID    512
#define NB     16
#define SEQ    2048
#define TLEN   4096
#define NSTEPS (TLEN - SEQ)
#define NBLK   128
#define NTHR   512
#define VSTRIDE 2049                       // padded row stride: 8 batches -> 8 distinct banks
#define REDSZ   2048
#define SMEM_FLOATS (B * VSTRIDE + REDSZ + 128)

// ---------------- persistent state (device globals; no allocs) ----------------
__device__ float g_h1[B * DIM];
__device__ float g_nxt[B * DIM];
__device__ float g_hist[2][B * DIM];       // ping-pong corrected "cur" history
__device__ float g_coef[2][B * NB];        // double-buffered coef accumulators
__device__ unsigned long long g_gen = 0;   // barrier generation (monotonic across replays)
__device__ unsigned int       g_cnt = 0;   // barrier arrival counter (self-resetting)

// ---------------- grid barrier ----------------
__device__ __forceinline__ unsigned long long ld_acq(unsigned long long* p) {
    unsigned long long v;
    asm volatile("ld.acquire.gpu.global.u64 %0, [%1];" : "=l"(v) : "l"(p) : "memory");
    return v;
}
__device__ __forceinline__ void st_rel(unsigned long long* p, unsigned long long v) {
    asm volatile("st.release.gpu.global.u64 [%0], %1;" :: "l"(p), "l"(v) : "memory");
}
__device__ __forceinline__ void grid_barrier() {
    __syncthreads();
    if (threadIdx.x == 0) {
        unsigned long long my = ld_acq(&g_gen);
        __threadfence();
        if (atomicAdd(&g_cnt, 1u) == NBLK - 1) {
            g_cnt = 0;                       // ordered before gen flip by st.release
            st_rel(&g_gen, my + 1);
        } else {
            while (ld_acq(&g_gen) == my) { __nanosleep(32); }
        }
    }
    __syncthreads();
}

// ---------------- prefix copy: out[:, 0:2048, :] = x ----------------
__global__ void copy_kernel(const float4* __restrict__ x4, float4* __restrict__ out4) {
    size_t q = (size_t)blockIdx.x * blockDim.x + threadIdx.x;   // 0 .. 8*2048*256-1
    int b = (int)(q >> 19);                 // 2048*256 float4 per batch
    size_t r = q & 524287;
    out4[((size_t)b << 20) + r] = x4[q];    // 4096*256 float4 per out batch
}

// ---------------- persistent extrapolation kernel ----------------
__global__ void __launch_bounds__(NTHR, 1)
extrap_kernel(const float* __restrict__ x,
              const float* __restrict__ basis,
              const float* __restrict__ W1,
              const float* __restrict__ b1,
              const float* __restrict__ W2,
              const float* __restrict__ b2,
              const float* __restrict__ D1,
              const float* __restrict__ bD1,
              const float* __restrict__ D2,
              const float* __restrict__ bD2,
              float* __restrict__ out)
{
    extern __shared__ float smem[];
    float* s_vin  = smem;                   // [B][VSTRIDE]: cur @ [0..1023], prev/h1/nxt @ [1024..2047]
    float* s_red  = smem + B * VSTRIDE;     // REDSZ floats reduction scratch
    float* s_coef = s_red + REDSZ;          // 128 floats

    const int bid = blockIdx.x;
    const int t   = threadIdx.x;

    for (int s = 0; s < NSTEPS; ++s) {
        // ================= prologue: materialize cur (corrected) & prev =================
        if (s == 0) {
            for (int idx = t; idx < B * DIM; idx += NTHR) {
                int b = idx >> 10, k = idx & (DIM - 1);
                s_vin[b * VSTRIDE + k]       = x[((size_t)b * SEQ + (SEQ - 1)) * DIM + k];
                s_vin[b * VSTRIDE + DIM + k] = x[((size_t)b * SEQ + (SEQ - 2)) * DIM + k];
            }
            if (t < 64) {                    // hist[0] = cur_0 (prev for step 1)
                int b = t >> 3, kk = bid * 8 + (t & 7);
                g_hist[0][b * DIM + kk] = x[((size_t)b * SEQ + (SEQ - 1)) * DIM + kk];
            }
            if (bid == 0 && t < 2 * B * NB) ((float*)g_coef)[t] = 0.f;
        } else {
            const int par = (s - 1) & 1;
            if (t < B * NB) s_coef[t] = g_coef[par][t] + b2[t & (NB - 1)];
            __syncthreads();
            #pragma unroll
            for (int pass = 0; pass < DIM / NTHR; ++pass) {
                int k = pass * NTHR + t;
                float bas[NB];
                #pragma unroll
                for (int c = 0; c < NB; ++c) bas[c] = basis[c * DIM + k];
                #pragma unroll
                for (int b = 0; b < B; ++b) {
                    float acc = g_nxt[b * DIM + k];
                    #pragma unroll
                    for (int c = 0; c < NB; ++c) acc += 0.1f * s_coef[b * NB + c] * bas[c];
                    s_vin[b * VSTRIDE + k]       = acc;                        // cur_s
                    s_vin[b * VSTRIDE + DIM + k] = g_hist[par][b * DIM + k];   // prev_s
                }
            }
            __syncthreads();
            if (t < 64) {                    // owner writes corrected row to hist + output
                int b = t >> 3, kk = bid * 8 + (t & 7);
                float v = s_vin[b * VSTRIDE + kk];
                g_hist[s & 1][b * DIM + kk] = v;
                out[((size_t)b * TLEN + (SEQ + s - 1)) * DIM + kk] = v;
            }
        }
        __syncthreads();

        // ================= phase 1: h1 = tanh([cur,prev] @ D1 + bD1), 8 cols/block =================
        {
            const int jbase = bid * 8;
            const int cg = t & 1;            // column group of 4
            const int b  = (t >> 1) & 7;
            const int ks = t >> 4;           // 0..31, 64 k each
            const float* vrow = s_vin + b * VSTRIDE;
            const int j0 = jbase + cg * 4;
            float a0 = 0.f, a1 = 0.f, a2 = 0.f, a3 = 0.f;
            const int k0 = ks * 64;
            #pragma unroll 8
            for (int k = k0; k < k0 + 64; ++k) {
                float xv = vrow[k];
                float4 w = __ldg(reinterpret_cast<const float4*>(D1 + ((size_t)k << 10) + j0));
                a0 += xv * w.x; a1 += xv * w.y; a2 += xv * w.z; a3 += xv * w.w;
            }
            reinterpret_cast<float4*>(s_red)[(cg * 8 + b) * 32 + ks] = make_float4(a0, a1, a2, a3);
        }
        __syncthreads();
        if (t < 64) {
            int pg = t >> 2, ci = t & 3;
            int cg = pg >> 3, b = pg & 7;
            float sum = 0.f;
            #pragma unroll
            for (int kk = 0; kk < 32; ++kk) sum += s_red[(pg * 32 + kk) * 4 + ci];
            int j = bid * 8 + cg * 4 + ci;
            g_h1[b * DIM + j] = tanhf(sum + bD1[j]);
        }
        grid_barrier();
        if (bid == 0 && t < B * NB) g_coef[(s + 1) & 1][t] = 0.f;   // safe: prologue reads done

        // stage h1 into smem (second half)
        for (int idx = t; idx < B * DIM; idx += NTHR) {
            int b = idx >> 10, j = idx & (DIM - 1);
            s_vin[b * VSTRIDE + DIM + j] = g_h1[idx];
        }
        __syncthreads();

        // ================= phase 2: nxt = cur + h1 @ D2 + bD2, 8 cols/block =================
        {
            const int ibase = bid * 8;
            const int cg = t & 1, b = (t >> 1) & 7, ks = t >> 4;   // 32 slices, 32 k each
            const float* hrow = s_vin + b * VSTRIDE + DIM;
            const int i0 = ibase + cg * 4;
            float a0 = 0.f, a1 = 0.f, a2 = 0.f, a3 = 0.f;
            const int k0 = ks * 32;
            #pragma unroll 8
            for (int k = k0; k < k0 + 32; ++k) {
                float hv = hrow[k];
                float4 w = __ldg(reinterpret_cast<const float4*>(D2 + ((size_t)k << 10) + i0));
                a0 += hv * w.x; a1 += hv * w.y; a2 += hv * w.z; a3 += hv * w.w;
            }
            reinterpret_cast<float4*>(s_red)[(cg * 8 + b) * 32 + ks] = make_float4(a0, a1, a2, a3);
        }
        __syncthreads();
        if (t < 64) {
            int pg = t >> 2, ci = t & 3;
            int cg = pg >> 3, b = pg & 7;
            float sum = 0.f;
            #pragma unroll
            for (int kk = 0; kk < 32; ++kk) sum += s_red[(pg * 32 + kk) * 4 + ci];
            int i = bid * 8 + cg * 4 + ci;
            g_nxt[b * DIM + i] = s_vin[b * VSTRIDE + i] + sum + bD2[i];
        }
        grid_barrier();

        // stage nxt into smem (second half)
        for (int idx = t; idx < B * DIM; idx += NTHR) {
            int b = idx >> 10, i = idx & (DIM - 1);
            s_vin[b * VSTRIDE + DIM + i] = g_nxt[idx];
        }
        __syncthreads();

        // ================= phase 3/4: g = gelu(nxt@W1+b1); coef += g@W2 (4 cols/block) =================
        {
            const int mbase = bid * 4;
            const int b = t & 7, ks = t >> 3;   // 64 slices, 16 k each
            const float* nrow = s_vin + b * VSTRIDE + DIM;
            float a0 = 0.f, a1 = 0.f, a2 = 0.f, a3 = 0.f;
            const int k0 = ks * 16;
            #pragma unroll
            for (int k = k0; k < k0 + 16; ++k) {
                float nv = nrow[k];
                float4 w = __ldg(reinterpret_cast<const float4*>(W1 + (size_t)k * HID + mbase));
                a0 += nv * w.x; a1 += nv * w.y; a2 += nv * w.z; a3 += nv * w.w;
            }
            reinterpret_cast<float4*>(s_red)[b * 64 + ks] = make_float4(a0, a1, a2, a3);
        }
        __syncthreads();
        if (t < 32) {
            int b = t >> 2, mi = t & 3;
            float sum = 0.f;
            #pragma unroll
            for (int kk = 0; kk < 64; ++kk) sum += s_red[(b * 64 + kk) * 4 + mi];
            int m = bid * 4 + mi;
            float z = sum + b1[m];
            s_coef[t] = 0.5f * z * (1.0f + erff(z * 0.70710678118654752f));  // exact gelu
        }
        __syncthreads();
        if (t < B * NB) {
            int b = t >> 4, c = t & (NB - 1);
            float acc = 0.f;
            #pragma unroll
            for (int mi = 0; mi < 4; ++mi)
                acc += s_coef[b * 4 + mi] * __ldg(W2 + (size_t)(bid * 4 + mi) * NB + c);
            atomicAdd(&g_coef[s & 1][t], acc);
        }
        grid_barrier();
    }

    // ================= epilogue: final corrected row (t = TLEN-1) =================
    {
        const int par = (NSTEPS - 1) & 1;
        if (t < B * NB) s_coef[t] = g_coef[par][t] + b2[t & (NB - 1)];
        __syncthreads();
        if (t < 64) {
            int b = t >> 3, kk = bid * 8 + (t & 7);
            float acc = g_nxt[b * DIM + kk];
            #pragma unroll
            for (int c = 0; c < NB; ++c) acc += 0.1f * s_coef[b * NB + c] * basis[c * DIM + kk];
            out[((size_t)b * TLEN + (TLEN - 1)) * DIM + kk] = acc;
        }
    }
}

// ---------------- launch ----------------
extern "C" void kernel_launch(void* const* d_in, const int* in_sizes, int n_in,
                              void* d_out, int out_size) {
    const float* x     = (const float*)d_in[0];
    const float* basis = (const float*)d_in[1];
    const float* W1    = (const float*)d_in[2];
    const float* b1    = (const float*)d_in[3];
    const float* W2    = (const float*)d_in[4];
    const float* b2v   = (const float*)d_in[5];
    const float* D1    = (const float*)d_in[6];
    const float* bD1   = (const float*)d_in[7];
    const float* D2    = (const float*)d_in[8];
    const float* bD2   = (const float*)d_in[9];
    float* out = (float*)d_out;

    // prefix: out[:, 0:2048, :] = x   (8*2048*256 float4 = 4096 * 1024 threads)
    copy_kernel<<<4096, 1024>>>((const float4*)x, (float4*)out);

    size_t smem_bytes = (size_t)SMEM_FLOATS * sizeof(float);   // ~74.3 KB
    cudaFuncSetAttribute(extrap_kernel, cudaFuncAttributeMaxDynamicSharedMemorySize,
                         (int)smem_bytes);
    extrap_kernel<<<NBLK, NTHR, smem_bytes>>>(x, basis, W1, b1, W2, b2v,
                                              D1, bD1, D2, bD2, out);
}

// round 4
// speedup vs baseline: 1.8557x; 1.8552x over previous
#include <cuda_runtime.h>
#include <math.h>

typedef unsigned long long ull;

#define B      8
#define DIM    1024
#define HID    512
#define NB     16
#define SEQ    2048
#define TLEN   4096
#define NSTEPS (TLEN - SEQ)
#define NBLK   128
#define NTHR   512
#define KP     1036                         // act row stride: 4-per-quad bank tiling
#define ACT_SLOT (B * KP)

// ---------------- persistent state ----------------
__device__ float g_h1[B * DIM];
__device__ float g_u[2][B * DIM];
__device__ float g_coef[2][B * NB];
__device__ ull           g_gen = 0;
__device__ unsigned int  g_cnt = 0;

// ---------------- packed f32x2 FMA ----------------
__device__ __forceinline__ void fma2(ull& d, ull a, ull b) {
    asm("fma.rn.f32x2 %0, %1, %2, %0;" : "+l"(d) : "l"(a), "l"(b));
}
__device__ __forceinline__ float f2sum(ull v) {
    float lo, hi;
    asm("mov.b64 {%0,%1}, %2;" : "=f"(lo), "=f"(hi) : "l"(v));
    return lo + hi;
}

// ---------------- grid barrier ----------------
__device__ __forceinline__ ull ld_acq(ull* p) {
    ull v; asm volatile("ld.acquire.gpu.global.u64 %0, [%1];" : "=l"(v) : "l"(p) : "memory");
    return v;
}
__device__ __forceinline__ void st_rel(ull* p, ull v) {
    asm volatile("st.release.gpu.global.u64 [%0], %1;" :: "l"(p), "l"(v) : "memory");
}
__device__ __forceinline__ void grid_barrier() {
    __syncthreads();
    if (threadIdx.x == 0) {
        ull my = ld_acq(&g_gen);
        __threadfence();
        if (atomicAdd(&g_cnt, 1u) == NBLK - 1) {
            g_cnt = 0;
            st_rel(&g_gen, my + 1);
        } else {
            while (ld_acq(&g_gen) == my) { __nanosleep(32); }
        }
    }
    __syncthreads();
}

// ---------------- prefix copy ----------------
__global__ void copy_kernel(const float4* __restrict__ x4, float4* __restrict__ out4) {
    size_t q = (size_t)blockIdx.x * blockDim.x + threadIdx.x;
    int b = (int)(q >> 19);
    size_t r = q & 524287;
    out4[((size_t)b << 20) + r] = x4[q];
}

// smem offsets (floats)
#define OFF_W1   0
#define OFF_W2   16384
#define OFF_W3   24576
#define OFF_ACT  28672
#define OFF_RED  45248
#define OFF_C1   46272
#define OFF_C2   46400
#define OFF_BAS  46528
#define OFF_BD1T 46656
#define OFF_BD1B 46784
#define OFF_G    46912
#define OFF_WC2  46944
#define OFF_BB   47008
#define SMEM_FLOATS 47048

__global__ void __launch_bounds__(NTHR, 1)
extrap_kernel(const float* __restrict__ x, const float* __restrict__ basis,
              const float* __restrict__ W1, const float* __restrict__ b1,
              const float* __restrict__ W2, const float* __restrict__ b2,
              const float* __restrict__ D1, const float* __restrict__ bD1,
              const float* __restrict__ D2, const float* __restrict__ bD2,
              float* __restrict__ out)
{
    extern __shared__ float sm[];
    float* s_w1   = sm + OFF_W1;    // [8 j][2048 k]   D1 slice (j-major)
    float* s_w2   = sm + OFF_W2;    // [8 i][1024 k]   D2 slice
    float* s_w3   = sm + OFF_W3;    // [4 m][1024 k]   W1 slice
    float* s_act  = sm + OFF_ACT;   // 2 slots x [8 b][KP]
    float* s_red  = sm + OFF_RED;   // reduction scratch
    float* s_c1   = sm + OFF_C1;    // c_{s-1} incl b2  [b*16+c]
    float* s_c2   = sm + OFF_C2;    // c_{s-2} incl b2
    float* s_bas  = sm + OFF_BAS;   // basis[c][own 8 dims]
    float* s_bd1t = sm + OFF_BD1T;  // (basis@D1t)[c][own 8 j]
    float* s_bd1b = sm + OFF_BD1B;
    float* s_g    = sm + OFF_G;     // gelu vals [b*4+ml]
    float* s_wc2  = sm + OFF_WC2;   // W2 slice [ml*16+cc]
    float* s_bb   = sm + OFF_BB;    // biases: bD1[0..7], bD2[8..15], b1[16..19], b2[20..35]

    const int bid = blockIdx.x;
    const int t   = threadIdx.x;
    const int b   = t & 7;
    const int kg  = t >> 3;          // 0..63

    // ================= init: weights -> smem =================
    for (int idx = t; idx < 8 * 2048; idx += NTHR) {
        int jl = idx & 7, kk = idx >> 3;
        s_w1[jl * 2048 + kk] = __ldg(D1 + (size_t)kk * DIM + bid * 8 + jl);
    }
    for (int idx = t; idx < 8 * 1024; idx += NTHR) {
        int il = idx & 7, kk = idx >> 3;
        s_w2[il * 1024 + kk] = __ldg(D2 + (size_t)kk * DIM + bid * 8 + il);
    }
    for (int idx = t; idx < 4 * 1024; idx += NTHR) {
        int ml = idx & 3, kk = idx >> 2;
        s_w3[ml * 1024 + kk] = __ldg(W1 + (size_t)kk * HID + bid * 4 + ml);
    }
    if (t < 128) s_bas[t] = __ldg(basis + (size_t)(t >> 3) * DIM + bid * 8 + (t & 7));
    if (t < 64)  s_wc2[t] = __ldg(W2 + (size_t)(bid * 4 + (t >> 4)) * NB + (t & 15));
    if (t >= 64 && t < 72)        s_bb[t - 64]      = __ldg(bD1 + bid * 8 + (t - 64));
    else if (t >= 72 && t < 80)   s_bb[t - 72 + 8]  = __ldg(bD2 + bid * 8 + (t - 72));
    else if (t >= 80 && t < 84)   s_bb[t - 80 + 16] = __ldg(b1 + bid * 4 + (t - 80));
    else if (t >= 84 && t < 100)  s_bb[t - 84 + 20] = __ldg(b2 + (t - 84));
    // initial acts: slot1 = u_{-1} = x[:,SEQ-1], slot0 = u_{-2} = x[:,SEQ-2]
    for (int g = t; g < 2048; g += NTHR) {
        int bb = g >> 8, kq = g & 255;
        float4 v1 = *reinterpret_cast<const float4*>(x + ((size_t)bb * SEQ + SEQ - 1) * DIM + kq * 4);
        float4 v0 = *reinterpret_cast<const float4*>(x + ((size_t)bb * SEQ + SEQ - 2) * DIM + kq * 4);
        *reinterpret_cast<float4*>(s_act + ACT_SLOT + bb * KP + kq * 4) = v1;
        *reinterpret_cast<float4*>(s_act + bb * KP + kq * 4) = v0;
    }
    __syncthreads();
    // BD1t/BD1b = basis @ D1t/D1b for this block's 8 columns (from smem weights)
    if (t < 256) {
        int half = t >> 7, c = (t >> 3) & 15, jl = t & 7;
        const float* wr = s_w1 + jl * 2048 + half * 1024;
        const float* br = basis + (size_t)c * DIM;
        float a0 = 0.f, a1 = 0.f, a2 = 0.f, a3 = 0.f;
        for (int k = 0; k < 1024; k += 4) {
            a0 += wr[k]     * __ldg(br + k);
            a1 += wr[k + 1] * __ldg(br + k + 1);
            a2 += wr[k + 2] * __ldg(br + k + 2);
            a3 += wr[k + 3] * __ldg(br + k + 3);
        }
        (half ? s_bd1b : s_bd1t)[c * 8 + jl] = (a0 + a1) + (a2 + a3);
    }
    __syncthreads();

    // ================= step loop =================
    for (int s = 0; s <= NSTEPS; ++s) {
        const int sA = s & 1;

        // ---- prologue: stage coef vectors (incl b2), write out row s-1 ----
        if (t < 128) {
            float b2v = s_bb[20 + (t & 15)];
            s_c1[t] = (s >= 1) ? g_coef[1 - sA][t] + b2v : 0.f;
            s_c2[t] = (s >= 2) ? g_coef[sA][t]     + b2v : 0.f;
        }
        __syncthreads();
        if (s > 0 && t < 64) {
            int il = t & 7, bb = t >> 3;
            int ig = bid * 8 + il;
            float corr = 0.f;
            #pragma unroll
            for (int c = 0; c < NB; ++c) corr += s_c1[bb * NB + c] * s_bas[c * 8 + il];
            float v = s_act[(1 - sA) * ACT_SLOT + bb * KP + ig] + 0.1f * corr;
            out[((size_t)bb * TLEN + SEQ + s - 1) * DIM + ig] = v;
        }
        if (s == NSTEPS) break;

        // ================= P1: z = u1@D1t + u2@D1b (+folded corrections), h1 = tanh =================
        {
            const float* actA = s_act + (1 - sA) * ACT_SLOT + b * KP;  // u_{s-1}
            const float* actB = s_act + sA * ACT_SLOT + b * KP;        // u_{s-2}
            ull acc[8];
            #pragma unroll
            for (int j = 0; j < 8; ++j) acc[j] = 0ull;
            #pragma unroll
            for (int half = 0; half < 2; ++half) {
                const float* act = half ? actB : actA;
                const float* wb  = s_w1 + half * 1024;
                #pragma unroll
                for (int c = 0; c < 4; ++c) {
                    const int k0 = c * 256 + kg * 4;
                    ulonglong2 a = *reinterpret_cast<const ulonglong2*>(act + k0);
                    #pragma unroll
                    for (int jl = 0; jl < 8; ++jl) {
                        ulonglong2 w = *reinterpret_cast<const ulonglong2*>(wb + jl * 2048 + k0);
                        fma2(acc[jl], w.x, a.x);
                        fma2(acc[jl], w.y, a.y);
                    }
                }
            }
            float r[8];
            #pragma unroll
            for (int jl = 0; jl < 8; ++jl) {
                r[jl] = f2sum(acc[jl]);
                r[jl] += __shfl_xor_sync(0xffffffffu, r[jl], 8);
                r[jl] += __shfl_xor_sync(0xffffffffu, r[jl], 16);
            }
            if ((t & 31) < 8) {
                int w = t >> 5;
                #pragma unroll
                for (int jl = 0; jl < 8; ++jl) s_red[(w * 8 + b) * 8 + jl] = r[jl];
            }
        }
        __syncthreads();
        if (t < 64) {
            int jl = t & 7, bb = t >> 3;
            float sum = 0.f;
            #pragma unroll
            for (int w = 0; w < 16; ++w) sum += s_red[(w * 8 + bb) * 8 + jl];
            float cd = 0.f;
            #pragma unroll
            for (int c = 0; c < NB; ++c)
                cd += s_c1[bb * NB + c] * s_bd1t[c * 8 + jl]
                    + s_c2[bb * NB + c] * s_bd1b[c * 8 + jl];
            float z = sum + 0.1f * cd + s_bb[jl];
            g_h1[bb * DIM + bid * 8 + jl] = tanhf(z);
        }
        grid_barrier();
        if (bid == 0 && t < 128) g_coef[sA][t] = 0.f;   // c_{s-2} consumed; reuse slot for c_s

        // ---- stage h1 -> slot sA ----
        #pragma unroll
        for (int r = 0; r < 4; ++r) {
            int g = r * NTHR + t;
            int bb = g >> 8, kq = g & 255;
            float4 v = *reinterpret_cast<const float4*>(g_h1 + bb * DIM + kq * 4);
            *reinterpret_cast<float4*>(s_act + sA * ACT_SLOT + bb * KP + kq * 4) = v;
        }
        __syncthreads();

        // ================= P2: u_s = u_{s-1} + 0.1 c1·basis + h1@D2 + bD2 =================
        {
            const float* act = s_act + sA * ACT_SLOT + b * KP;
            ull acc[8];
            #pragma unroll
            for (int j = 0; j < 8; ++j) acc[j] = 0ull;
            #pragma unroll
            for (int c = 0; c < 4; ++c) {
                const int k0 = c * 256 + kg * 4;
                ulonglong2 a = *reinterpret_cast<const ulonglong2*>(act + k0);
                #pragma unroll
                for (int il = 0; il < 8; ++il) {
                    ulonglong2 w = *reinterpret_cast<const ulonglong2*>(s_w2 + il * 1024 + k0);
                    fma2(acc[il], w.x, a.x);
                    fma2(acc[il], w.y, a.y);
                }
            }
            float r[8];
            #pragma unroll
            for (int il = 0; il < 8; ++il) {
                r[il] = f2sum(acc[il]);
                r[il] += __shfl_xor_sync(0xffffffffu, r[il], 8);
                r[il] += __shfl_xor_sync(0xffffffffu, r[il], 16);
            }
            if ((t & 31) < 8) {
                int w = t >> 5;
                #pragma unroll
                for (int il = 0; il < 8; ++il) s_red[(w * 8 + b) * 8 + il] = r[il];
            }
        }
        __syncthreads();
        if (t < 64) {
            int il = t & 7, bb = t >> 3;
            int ig = bid * 8 + il;
            float sum = 0.f;
            #pragma unroll
            for (int w = 0; w < 16; ++w) sum += s_red[(w * 8 + bb) * 8 + il];
            float corr = 0.f;
            #pragma unroll
            for (int c = 0; c < NB; ++c) corr += s_c1[bb * NB + c] * s_bas[c * 8 + il];
            float u = s_act[(1 - sA) * ACT_SLOT + bb * KP + ig] + 0.1f * corr + sum + s_bb[8 + il];
            g_u[sA][bb * DIM + ig] = u;
        }
        grid_barrier();

        // ---- stage u_s -> slot sA (overwrites h1) ----
        #pragma unroll
        for (int r = 0; r < 4; ++r) {
            int g = r * NTHR + t;
            int bb = g >> 8, kq = g & 255;
            float4 v = *reinterpret_cast<const float4*>(g_u[sA] + bb * DIM + kq * 4);
            *reinterpret_cast<float4*>(s_act + sA * ACT_SLOT + bb * KP + kq * 4) = v;
        }
        __syncthreads();

        // ================= P3: c_s += gelu(u_s@W1+b1)[4 m] @ W2 =================
        {
            const float* act = s_act + sA * ACT_SLOT + b * KP;
            ull acc[4];
            #pragma unroll
            for (int m = 0; m < 4; ++m) acc[m] = 0ull;
            #pragma unroll
            for (int c = 0; c < 4; ++c) {
                const int k0 = c * 256 + kg * 4;
                ulonglong2 a = *reinterpret_cast<const ulonglong2*>(act + k0);
                #pragma unroll
                for (int ml = 0; ml < 4; ++ml) {
                    ulonglong2 w = *reinterpret_cast<const ulonglong2*>(s_w3 + ml * 1024 + k0);
                    fma2(acc[ml], w.x, a.x);
                    fma2(acc[ml], w.y, a.y);
                }
            }
            float r[4];
            #pragma unroll
            for (int ml = 0; ml < 4; ++ml) {
                r[ml] = f2sum(acc[ml]);
                r[ml] += __shfl_xor_sync(0xffffffffu, r[ml], 8);
                r[ml] += __shfl_xor_sync(0xffffffffu, r[ml], 16);
            }
            if ((t & 31) < 8) {
                int w = t >> 5;
                #pragma unroll
                for (int ml = 0; ml < 4; ++ml) s_red[(w * 8 + b) * 4 + ml] = r[ml];
            }
        }
        __syncthreads();
        if (t < 32) {
            int ml = t & 3, bb = t >> 2;
            float sum = 0.f;
            #pragma unroll
            for (int w = 0; w < 16; ++w) sum += s_red[(w * 8 + bb) * 4 + ml];
            float z = sum + s_bb[16 + ml];
            s_g[bb * 4 + ml] = 0.5f * z * (1.0f + erff(z * 0.70710678118654752f));
        }
        __syncthreads();
        if (t < 128) {
            int bb = t >> 4, cc = t & 15;
            float a = 0.f;
            #pragma unroll
            for (int ml = 0; ml < 4; ++ml) a += s_g[bb * 4 + ml] * s_wc2[ml * NB + cc];
            atomicAdd(&g_coef[sA][bb * NB + cc], a);
        }
        grid_barrier();
    }
}

// ---------------- launch ----------------
extern "C" void kernel_launch(void* const* d_in, const int* in_sizes, int n_in,
                              void* d_out, int out_size) {
    const float* x     = (const float*)d_in[0];
    const float* basis = (const float*)d_in[1];
    const float* W1    = (const float*)d_in[2];
    const float* b1    = (const float*)d_in[3];
    const float* W2    = (const float*)d_in[4];
    const float* b2v   = (const float*)d_in[5];
    const float* D1    = (const float*)d_in[6];
    const float* bD1   = (const float*)d_in[7];
    const float* D2    = (const float*)d_in[8];
    const float* bD2   = (const float*)d_in[9];
    float* out = (float*)d_out;

    copy_kernel<<<4096, 1024>>>((const float4*)x, (float4*)out);

    size_t smem_bytes = (size_t)SMEM_FLOATS * sizeof(float);   // ~188 KB
    cudaFuncSetAttribute(extrap_kernel, cudaFuncAttributeMaxDynamicSharedMemorySize,
                         (int)smem_bytes);
    extrap_kernel<<<NBLK, NTHR, smem_bytes>>>(x, basis, W1, b1, W2, b2v,
                                              D1, bD1, D2, bD2, out);
}